// round 7
// baseline (speedup 1.0000x reference)
#include <cuda_runtime.h>
#include <cuda_bf16.h>
#include <cstdint>

#define NN   50000
#define NE   800000
#define H    256
#define NL   3
#define NIDX 8192   // N_PAIRS * 2

// ---------------- scratch (static device globals; no allocation) -------------
__device__ float g_h[(size_t)NN * H];     // 51.2 MB  (post-conv features)
__device__ float g_x[(size_t)NN * H];     // 51.2 MB  (aggregated features)
__device__ int   g_deg[NN];
__device__ int   g_fill[NN];
__device__ int   g_start[NN];             // exclusive CSR row start
__device__ int   g_csr[NE];               // src node per dst-sorted slot
__device__ float g_W0[NL * H * H];        // f0_w @ conv_w
__device__ float g_W1[NL * H * H];        // f1_w @ conv_w
__device__ float g_B0[NL * H];            // f0_b @ conv_w + conv_b
__device__ float g_B1[NL * H];            // f1_b @ conv_w + conv_b
// packed bf16 split weights: [layer][half][split hi/lo][n=128][k=256] dense bf16
__device__ uint32_t g_Bpack[NL * 2 * 2 * 16384];

// ---------------- CSR construction ------------------------------------------
__global__ void k_zero() {
    int i = blockIdx.x * blockDim.x + threadIdx.x;
    if (i < NN) { g_deg[i] = 0; g_fill[i] = 0; }
}

__global__ void k_hist(const int* __restrict__ dst) {
    int e = blockIdx.x * blockDim.x + threadIdx.x;
    if (e < NE) atomicAdd(&g_deg[dst[e]], 1);
}

__global__ void k_scan() {
    __shared__ int s1[1024];
    __shared__ int s2[1024];
    int run = 0;
    int t = threadIdx.x;
    for (int base = 0; base < NN; base += 1024) {
        int i = base + t;
        int v = (i < NN) ? g_deg[i] : 0;
        s1[t] = v;
        __syncthreads();
        int* a = s1; int* b = s2;
        #pragma unroll
        for (int off = 1; off < 1024; off <<= 1) {
            int x = a[t];
            if (t >= off) x += a[t - off];
            b[t] = x;
            __syncthreads();
            int* tmp = a; a = b; b = tmp;
        }
        int incl = a[t];
        if (i < NN) g_start[i] = run + incl - v;
        run += a[1023];
        __syncthreads();
    }
}

__global__ void k_scatter(const int* __restrict__ src, const int* __restrict__ dst) {
    int e = blockIdx.x * blockDim.x + threadIdx.x;
    if (e < NE) {
        int d = dst[e];
        int slot = g_start[d] + atomicAdd(&g_fill[d], 1);
        g_csr[slot] = src[e];
    }
}

// ---------------- weight folding --------------------------------------------
__global__ void k_fusew(const float* __restrict__ f0w, const float* __restrict__ f1w,
                        const float* __restrict__ convw) {
    int l = blockIdx.y, which = blockIdx.z;
    const float* A = (which ? f1w : f0w) + (size_t)l * H * H;
    const float* B = convw + (size_t)l * H * H;
    float* C = (which ? g_W1 : g_W0) + (size_t)l * H * H;
    int i = blockIdx.x, j = threadIdx.x;
    float acc = 0.f;
    #pragma unroll 8
    for (int k = 0; k < H; k++) acc += A[i * H + k] * B[k * H + j];
    C[i * H + j] = acc;
}

__global__ void k_fuseb(const float* __restrict__ f0b, const float* __restrict__ f1b,
                        const float* __restrict__ convw, const float* __restrict__ convb) {
    int l = blockIdx.y, which = blockIdx.z;
    const float* bb = (which ? f1b : f0b) + l * H;
    const float* B  = convw + (size_t)l * H * H;
    float* out = (which ? g_B1 : g_B0) + l * H;
    int j = threadIdx.x;
    float acc = convb[l * H + j];
    #pragma unroll 8
    for (int k = 0; k < H; k++) acc += bb[k] * B[k * H + j];
    out[j] = acc;
}

// ---- pack folded W0 into bf16 hi/lo images, dense [n][k] (N-major, K contig)
__global__ void k_packB() {
    int lh = blockIdx.x;           // 0..NL*2-1  (= layer*2 + half)
    int l = lh >> 1, half = lh & 1;
    const float* W = g_W0 + (size_t)l * H * H;
    unsigned short* out = (unsigned short*)g_Bpack;
    size_t base_hi = ((size_t)lh * 2 + 0) * 32768;   // u16 units
    size_t base_lo = ((size_t)lh * 2 + 1) * 32768;
    for (int e = threadIdx.x; e < 128 * 256; e += blockDim.x) {
        int n = e >> 8;            // 0..127
        int k = e & 255;           // 0..255
        float v = W[k * H + half * 128 + n];
        __nv_bfloat16 hb = __float2bfloat16(v);
        float r = v - __bfloat162float(hb);
        __nv_bfloat16 lb = __float2bfloat16(r);
        out[base_hi + n * 256 + k] = *(unsigned short*)&hb;
        out[base_lo + n * 256 + k] = *(unsigned short*)&lb;
    }
}

// ================= mma.sync split-bf16 GEMM ==================================
// C[M,256] = A[M,256] @ W + bias.  Per CTA: 128 rows x 128 cols, K=256.
// 8 warps, warp tile 64x32.  3 products: Ahi*Bhi + Ahi*Blo + Alo*Bhi.
// SMEM: B [2 splits][128 n][264 k] bf16 ; A double-buffered [2][2 splits][128][72] bf16

#define B_STRIDE 528                      // 264 bf16 * 2B
#define A_STRIDE 144                      // 72 bf16 * 2B
#define SM_B     0
#define B_SPLIT  67584                    // 128 * 528
#define SM_A     135168                   // 2 * B_SPLIT
#define A_BUF    36864                    // 2 splits * 128 * 144
#define A_SPLIT  18432                    // 128 * 144
#define SM2_TOTAL (SM_A + 2 * A_BUF)      // 208896 B

__device__ __forceinline__ uint32_t smem_u32(const void* p) {
    uint32_t a;
    asm("{ .reg .u64 t; cvta.to.shared.u64 t, %1; cvt.u32.u64 %0, t; }" : "=r"(a) : "l"(p));
    return a;
}

#define LDSM_X4(r, addr)                                                        \
    asm volatile("ldmatrix.sync.aligned.m8n8.x4.shared.b16 {%0,%1,%2,%3}, [%4];" \
        : "=r"((r)[0]), "=r"((r)[1]), "=r"((r)[2]), "=r"((r)[3]) : "r"(addr))

#define MMA_BF16(c, a, b0, b1)                                                  \
    asm volatile("mma.sync.aligned.m16n8k16.row.col.f32.bf16.bf16.f32 "         \
        "{%0,%1,%2,%3},{%4,%5,%6,%7},{%8,%9},{%0,%1,%2,%3};"                    \
        : "+f"((c)[0]), "+f"((c)[1]), "+f"((c)[2]), "+f"((c)[3])                 \
        : "r"((a)[0]), "r"((a)[1]), "r"((a)[2]), "r"((a)[3]), "r"(b0), "r"(b1))

__global__ __launch_bounds__(256, 1) void k_gemm_mma(
    const float* __restrict__ A, const uint32_t* __restrict__ Bpk_l,
    const float* __restrict__ bias, float* __restrict__ C, int M) {
    extern __shared__ char smem[];
    const uint32_t smem_base = smem_u32(smem);
    const int tid  = threadIdx.x;
    const int wid  = tid >> 5;
    const int lane = tid & 31;
    const int bm = blockIdx.x * 128;
    const int bn = blockIdx.y * 128;
    const int mblk = (wid & 1) * 64;
    const int nblk = (wid >> 1) * 32;

    // ---- copy B images (hi, lo) gmem -> smem with 8-bf16 row padding ----
    {
        const uint4* src = (const uint4*)(Bpk_l + (size_t)blockIdx.y * 32768);
        #pragma unroll
        for (int s = 0; s < 2; s++) {
            for (int i = tid; i < 128 * 32; i += 256) {
                int n = i >> 5, kc = i & 31;
                *(uint4*)(smem + SM_B + s * B_SPLIT + n * B_STRIDE + kc * 16) =
                    src[s * 4096 + i];
            }
        }
    }

    // ---- A chunk prefetch helpers (chunk = 64 K-cols) ----
    const int prow  = tid >> 1;          // 0..127
    const int pslot = (tid & 1) * 32;    // K sub-offset
    const int growp = bm + prow;
    float4 pf[8];

    auto load_chunk = [&](int c) {
        const float* ap = A + (size_t)growp * H + c * 64 + pslot;
        #pragma unroll
        for (int i = 0; i < 8; i++) {
            pf[i] = (growp < M) ? *(const float4*)(ap + i * 4)
                                : make_float4(0.f, 0.f, 0.f, 0.f);
        }
    };
    auto store_chunk = [&](int buf) {
        char* hb = smem + SM_A + buf * A_BUF + prow * A_STRIDE + pslot * 2;
        char* lb = hb + A_SPLIT;
        #pragma unroll
        for (int i = 0; i < 8; i++) {
            float4 v = pf[i];
            __nv_bfloat16 h0 = __float2bfloat16(v.x);
            __nv_bfloat16 h1 = __float2bfloat16(v.y);
            __nv_bfloat16 h2 = __float2bfloat16(v.z);
            __nv_bfloat16 h3 = __float2bfloat16(v.w);
            __nv_bfloat16 l0 = __float2bfloat16(v.x - __bfloat162float(h0));
            __nv_bfloat16 l1 = __float2bfloat16(v.y - __bfloat162float(h1));
            __nv_bfloat16 l2 = __float2bfloat16(v.z - __bfloat162float(h2));
            __nv_bfloat16 l3 = __float2bfloat16(v.w - __bfloat162float(h3));
            __nv_bfloat162 p;
            uint2 ho, lo_;
            p.x = h0; p.y = h1; ho.x = *(uint32_t*)&p;
            p.x = h2; p.y = h3; ho.y = *(uint32_t*)&p;
            p.x = l0; p.y = l1; lo_.x = *(uint32_t*)&p;
            p.x = l2; p.y = l3; lo_.y = *(uint32_t*)&p;
            *(uint2*)(hb + i * 8) = ho;
            *(uint2*)(lb + i * 8) = lo_;
        }
    };

    float acc[4][4][4];
    #pragma unroll
    for (int a = 0; a < 4; a++)
        #pragma unroll
        for (int b = 0; b < 4; b++)
            #pragma unroll
            for (int c = 0; c < 4; c++) acc[a][b][c] = 0.f;

    // ldmatrix per-lane address components
    const int lrow  = (lane & 7) + ((lane >> 3) & 1) * 8;  // row within 16
    const int lcolt = (lane >> 4) * 8;                     // k sub-tile (0 or 8)

    load_chunk(0);
    store_chunk(0);
    __syncthreads();

    for (int c = 0; c < 4; c++) {
        if (c < 3) load_chunk(c + 1);
        const int buf = c & 1;
        const uint32_t abase_hi = smem_base + SM_A + buf * A_BUF;
        const uint32_t abase_lo = abase_hi + A_SPLIT;
        const uint32_t bbase_hi = smem_base + SM_B;
        const uint32_t bbase_lo = bbase_hi + B_SPLIT;

        #pragma unroll
        for (int ks = 0; ks < 4; ks++) {
            const int k0 = ks * 16;                 // within-chunk k offset
            const int kg = c * 64 + k0;             // global k offset for B
            uint32_t ahi[4][4], alo[4][4], bh[2][4], bl[2][4];
            #pragma unroll
            for (int mi = 0; mi < 4; mi++) {
                uint32_t ao = (mblk + mi * 16 + lrow) * A_STRIDE + (k0 + lcolt) * 2;
                LDSM_X4(ahi[mi], abase_hi + ao);
                LDSM_X4(alo[mi], abase_lo + ao);
            }
            #pragma unroll
            for (int nb = 0; nb < 2; nb++) {
                uint32_t bo = (nblk + nb * 16 + lrow) * B_STRIDE + (kg + lcolt) * 2;
                LDSM_X4(bh[nb], bbase_hi + bo);
                LDSM_X4(bl[nb], bbase_lo + bo);
            }
            #pragma unroll
            for (int mi = 0; mi < 4; mi++) {
                #pragma unroll
                for (int nt = 0; nt < 4; nt++) {
                    const int nb = nt >> 1, sel = nt & 1;
                    uint32_t b0h = bh[nb][sel], b1h = bh[nb][sel + 2];
                    uint32_t b0l = bl[nb][sel], b1l = bl[nb][sel + 2];
                    MMA_BF16(acc[mi][nt], ahi[mi], b0h, b1h);
                    MMA_BF16(acc[mi][nt], ahi[mi], b0l, b1l);
                    MMA_BF16(acc[mi][nt], alo[mi], b0h, b1h);
                }
            }
        }
        __syncthreads();
        if (c < 3) {
            store_chunk((c + 1) & 1);
            __syncthreads();
        }
    }

    // ---- epilogue: frag c0,c1 -> (row, 2col); c2,c3 -> (row+8, 2col) ----
    {
        const int r0 = lane >> 2;
        const int c0 = (lane & 3) * 2;
        #pragma unroll
        for (int mi = 0; mi < 4; mi++) {
            #pragma unroll
            for (int nt = 0; nt < 4; nt++) {
                int col = bn + nblk + nt * 8 + c0;
                float2 bv = *(const float2*)(bias + col);
                int row = bm + mblk + mi * 16 + r0;
                if (row < M) {
                    float2 o;
                    o.x = acc[mi][nt][0] + bv.x;
                    o.y = acc[mi][nt][1] + bv.y;
                    *(float2*)(C + (size_t)row * H + col) = o;
                }
                if (row + 8 < M) {
                    float2 o;
                    o.x = acc[mi][nt][2] + bv.x;
                    o.y = acc[mi][nt][3] + bv.y;
                    *(float2*)(C + (size_t)(row + 8) * H + col) = o;
                }
            }
        }
    }
}

// ---- gather/scatter GEMM for the labeled rows (8192 rows, FFMA is fine) -----
__global__ __launch_bounds__(256) void k_gemm_idx(const float* __restrict__ A,
                                                  const float* __restrict__ W,
                                                  const float* __restrict__ bias,
                                                  float* __restrict__ C,
                                                  const int* __restrict__ rows, int M) {
    __shared__ float As[16][128];
    __shared__ float Bs[16][64];
    const int bm = blockIdx.x * 128;
    const int bn = blockIdx.y * 64;
    const int tid = threadIdx.x;
    const int tx = tid & 15;
    const int ty = tid >> 4;
    const int r   = tid >> 1;
    const int kcb = (tid & 1) * 8;
    const int brow = tid >> 4;
    const int bcol = (tid & 15) << 2;

    int arow = (bm + r < M) ? rows[bm + r] : 0;

    float acc[8][4];
    #pragma unroll
    for (int i = 0; i < 8; i++)
        #pragma unroll
        for (int j = 0; j < 4; j++) acc[i][j] = 0.f;

    for (int k0 = 0; k0 < H; k0 += 16) {
        #pragma unroll
        for (int u = 0; u < 2; u++) {
            int kc = kcb + u * 4;
            float4 v = make_float4(0.f, 0.f, 0.f, 0.f);
            if (bm + r < M) v = *(const float4*)(A + (size_t)arow * H + k0 + kc);
            As[kc + 0][r] = v.x; As[kc + 1][r] = v.y;
            As[kc + 2][r] = v.z; As[kc + 3][r] = v.w;
        }
        *(float4*)&Bs[brow][bcol] = *(const float4*)(W + (size_t)(k0 + brow) * H + bn + bcol);
        __syncthreads();
        #pragma unroll
        for (int k = 0; k < 16; k++) {
            float a[8], b[4];
            *(float4*)&a[0] = *(float4*)&As[k][ty * 8];
            *(float4*)&a[4] = *(float4*)&As[k][ty * 8 + 4];
            *(float4*)&b[0] = *(float4*)&Bs[k][tx * 4];
            #pragma unroll
            for (int i = 0; i < 8; i++)
                #pragma unroll
                for (int j = 0; j < 4; j++)
                    acc[i][j] += a[i] * b[j];
        }
        __syncthreads();
    }
    float4 bv = *(const float4*)(bias + bn + tx * 4);
    #pragma unroll
    for (int i = 0; i < 8; i++) {
        int m = bm + ty * 8 + i;
        if (m < M) {
            int crow = rows[m];
            float4 o;
            o.x = acc[i][0] + bv.x; o.y = acc[i][1] + bv.y;
            o.z = acc[i][2] + bv.z; o.w = acc[i][3] + bv.w;
            *(float4*)(C + (size_t)crow * H + bn + tx * 4) = o;
        }
    }
}

// ---------------- aggregation: x[v] = sum over in-edges of h[src] ------------
__global__ __launch_bounds__(256) void k_aggr() {
    int w = (blockIdx.x * blockDim.x + threadIdx.x) >> 5;
    int lane = threadIdx.x & 31;
    if (w >= NN) return;
    int s = g_start[w];
    int e = s + g_deg[w];
    const float4* __restrict__ h4 = (const float4*)g_h;
    float4 a0 = make_float4(0.f, 0.f, 0.f, 0.f);
    float4 a1 = make_float4(0.f, 0.f, 0.f, 0.f);
    #pragma unroll 4
    for (int i = s; i < e; i++) {
        int src = __ldg(&g_csr[i]);
        float4 v0 = h4[(size_t)src * 64 + lane];
        float4 v1 = h4[(size_t)src * 64 + 32 + lane];
        a0.x += v0.x; a0.y += v0.y; a0.z += v0.z; a0.w += v0.w;
        a1.x += v1.x; a1.y += v1.y; a1.z += v1.z; a1.w += v1.w;
    }
    float4* x4 = (float4*)g_x;
    x4[(size_t)w * 64 + lane] = a0;
    x4[(size_t)w * 64 + 32 + lane] = a1;
}

// ---------------- final gather: out[r] = x[pos[r]] ---------------------------
__global__ void k_out(const int* __restrict__ pos, float* __restrict__ out) {
    int rr = blockIdx.x;
    int t = threadIdx.x;
    int node = pos[rr];
    ((float4*)out)[(size_t)rr * 64 + t] = ((const float4*)g_x)[(size_t)node * 64 + t];
}

// ---------------- launch -----------------------------------------------------
extern "C" void kernel_launch(void* const* d_in, const int* in_sizes, int n_in,
                              void* d_out, int out_size) {
    const float* x     = (const float*)d_in[0];
    const float* f0w   = (const float*)d_in[1];
    const float* f0b   = (const float*)d_in[2];
    const float* f1w   = (const float*)d_in[3];
    const float* f1b   = (const float*)d_in[4];
    const float* convw = (const float*)d_in[5];
    const float* convb = (const float*)d_in[6];
    const int*   esrc  = (const int*)d_in[7];
    const int*   edst  = (const int*)d_in[8];
    const int*   pos   = (const int*)d_in[9];
    float* out = (float*)d_out;

    static float *hbuf = nullptr, *xbuf = nullptr, *W1, *B0, *B1;
    static uint32_t* Bpk = nullptr;
    if (!hbuf) {
        cudaGetSymbolAddress((void**)&hbuf, g_h);
        cudaGetSymbolAddress((void**)&xbuf, g_x);
        cudaGetSymbolAddress((void**)&W1, g_W1);
        cudaGetSymbolAddress((void**)&B0, g_B0);
        cudaGetSymbolAddress((void**)&B1, g_B1);
        cudaGetSymbolAddress((void**)&Bpk, g_Bpack);
        cudaFuncSetAttribute(k_gemm_mma, cudaFuncAttributeMaxDynamicSharedMemorySize, SM2_TOTAL);
    }

    // CSR build
    k_zero<<<(NN + 255) / 256, 256>>>();
    k_hist<<<(NE + 255) / 256, 256>>>(edst);
    k_scan<<<1, 1024>>>();
    k_scatter<<<(NE + 255) / 256, 256>>>(esrc, edst);

    // fold (f0,f1) through conv, then pack W0 for mma
    k_fusew<<<dim3(H, NL, 2), H>>>(f0w, f1w, convw);
    k_fuseb<<<dim3(1, NL, 2), H>>>(f0b, f1b, convw, convb);
    k_packB<<<NL * 2, 256>>>();

    const float* xin = x;
    for (int l = 0; l < NL; l++) {
        k_gemm_mma<<<dim3((NN + 127) / 128, 2), 256, SM2_TOTAL>>>(
            xin, Bpk + (size_t)l * 65536, B0 + l * H, hbuf, NN);
        k_gemm_idx<<<dim3(NIDX / 128, H / 64), 256>>>(
            xin, W1 + (size_t)l * H * H, B1 + l * H, hbuf, pos, NIDX);
        k_aggr<<<(NN * 32 + 255) / 256, 256>>>();
        xin = xbuf;
    }
    k_out<<<NIDX, 64>>>(pos, out);
}

// round 8
// speedup vs baseline: 1.3861x; 1.3861x over previous
#include <cuda_runtime.h>
#include <cuda_bf16.h>
#include <cstdint>

#define NN   50000
#define NE   800000
#define H    256
#define NL   3
#define NIDX 8192   // N_PAIRS * 2

// ---------------- scratch (static device globals; no allocation) -------------
__device__ float g_h[(size_t)NN * H];     // 51.2 MB  (post-conv features)
__device__ float g_x[(size_t)NN * H];     // 51.2 MB  (aggregated features)
__device__ int   g_deg[NN];
__device__ int   g_fill[NN];
__device__ int   g_start[NN];             // exclusive CSR row start
__device__ int   g_blksum[64];            // per-block scan partials
__device__ int   g_csr[NE];               // src node per dst-sorted slot
__device__ float g_W0[NL * H * H];        // f0_w @ conv_w
__device__ float g_W1[NL * H * H];        // f1_w @ conv_w
__device__ float g_B0[NL * H];            // f0_b @ conv_w + conv_b
__device__ float g_B1[NL * H];            // f1_b @ conv_w + conv_b

// ---------------- packed fp32x2 helpers (Blackwell base ISA) -----------------
__device__ __forceinline__ void ffma2(unsigned long long& d, unsigned long long a,
                                      unsigned long long b) {
    asm("fma.rn.f32x2 %0, %1, %2, %3;" : "=l"(d) : "l"(a), "l"(b), "l"(d));
}
__device__ __forceinline__ unsigned long long bcast2(float x) {
    unsigned long long r;
    asm("mov.b64 %0, {%1, %1};" : "=l"(r) : "f"(x));
    return r;
}

// ---------------- CSR construction ------------------------------------------
__global__ void k_zero() {
    int i = blockIdx.x * blockDim.x + threadIdx.x;
    if (i < NN) { g_deg[i] = 0; g_fill[i] = 0; }
}

__global__ void k_hist(const int* __restrict__ dst) {
    int e = blockIdx.x * blockDim.x + threadIdx.x;
    if (e < NE) atomicAdd(&g_deg[dst[e]], 1);
}

// phase 1: per-block (1024) inclusive scan -> local exclusive + block total
__global__ void k_scan1() {
    __shared__ int s1[1024];
    __shared__ int s2[1024];
    int t = threadIdx.x;
    int i = blockIdx.x * 1024 + t;
    int v = (i < NN) ? g_deg[i] : 0;
    s1[t] = v;
    __syncthreads();
    int* a = s1; int* b = s2;
    #pragma unroll
    for (int off = 1; off < 1024; off <<= 1) {
        int x = a[t];
        if (t >= off) x += a[t - off];
        b[t] = x;
        __syncthreads();
        int* tmp = a; a = b; b = tmp;
    }
    int incl = a[t];
    if (i < NN) g_start[i] = incl - v;           // block-local exclusive
    if (t == 1023) g_blksum[blockIdx.x] = incl;  // block total
}

// phase 2: exclusive scan of 49 block totals (single block)
__global__ void k_scan2() {
    __shared__ int s[64];
    int t = threadIdx.x;                 // 64 threads
    int v = (t < 49) ? g_blksum[t] : 0;
    s[t] = v;
    __syncthreads();
    #pragma unroll
    for (int off = 1; off < 64; off <<= 1) {
        int x = s[t];
        int y = (t >= off) ? s[t - off] : 0;
        __syncthreads();
        s[t] = x + y;
        __syncthreads();
    }
    if (t < 49) g_blksum[t] = s[t] - v;  // exclusive
}

// phase 3: add block offsets
__global__ void k_scan3() {
    int i = blockIdx.x * 1024 + threadIdx.x;
    if (i < NN) g_start[i] += g_blksum[blockIdx.x];
}

__global__ void k_scatter(const int* __restrict__ src, const int* __restrict__ dst) {
    int e = blockIdx.x * blockDim.x + threadIdx.x;
    if (e < NE) {
        int d = dst[e];
        int slot = g_start[d] + atomicAdd(&g_fill[d], 1);
        g_csr[slot] = src[e];
    }
}

// ---------------- weight folding:  W = A @ conv_w,  b' = b @ conv_w + conv_b -
__global__ void k_fusew(const float* __restrict__ f0w, const float* __restrict__ f1w,
                        const float* __restrict__ convw) {
    int l = blockIdx.y, which = blockIdx.z;
    const float* A = (which ? f1w : f0w) + (size_t)l * H * H;
    const float* B = convw + (size_t)l * H * H;
    float* C = (which ? g_W1 : g_W0) + (size_t)l * H * H;
    int i = blockIdx.x, j = threadIdx.x;
    float acc = 0.f;
    #pragma unroll 8
    for (int k = 0; k < H; k++) acc += A[i * H + k] * B[k * H + j];
    C[i * H + j] = acc;
}

__global__ void k_fuseb(const float* __restrict__ f0b, const float* __restrict__ f1b,
                        const float* __restrict__ convw, const float* __restrict__ convb) {
    int l = blockIdx.y, which = blockIdx.z;
    const float* bb = (which ? f1b : f0b) + l * H;
    const float* B  = convw + (size_t)l * H * H;
    float* out = (which ? g_B1 : g_B0) + l * H;
    int j = threadIdx.x;
    float acc = convb[l * H + j];
    #pragma unroll 8
    for (int k = 0; k < H; k++) acc += bb[k] * B[k * H + j];
    out[j] = acc;
}

// ---------------- main GEMM: C[M,256] = A[M,256] @ W[256,256] + bias ---------
// BM=128 BN=64 BK=16, 256 threads, 8x4 per thread, fp32x2 packed along M
__global__ __launch_bounds__(256) void k_gemm(const float* __restrict__ A,
                                              const float* __restrict__ W,
                                              const float* __restrict__ bias,
                                              float* __restrict__ C, int M) {
    __shared__ float As[16][128];
    __shared__ float Bs[16][64];
    const int bm = blockIdx.x * 128;
    const int bn = blockIdx.y * 64;
    const int tid = threadIdx.x;
    const int tx = tid & 15;
    const int ty = tid >> 4;
    const int r   = tid >> 1;           // A-tile row this thread loads
    const int kcb = (tid & 1) * 8;      // A-tile k base
    const int brow = tid >> 4;          // B-tile row
    const int bcol = (tid & 15) << 2;   // B-tile col

    // acc[p][j] = packed {C[row 2p], C[row 2p+1]} for col j  (rows rel. ty*8)
    unsigned long long acc[4][4];
    #pragma unroll
    for (int p = 0; p < 4; p++)
        #pragma unroll
        for (int j = 0; j < 4; j++) acc[p][j] = 0ull;

    for (int k0 = 0; k0 < H; k0 += 16) {
        #pragma unroll
        for (int u = 0; u < 2; u++) {
            int kc = kcb + u * 4;
            int row = bm + r;
            float4 v = make_float4(0.f, 0.f, 0.f, 0.f);
            if (row < M) v = *(const float4*)(A + (size_t)row * H + k0 + kc);
            As[kc + 0][r] = v.x; As[kc + 1][r] = v.y;
            As[kc + 2][r] = v.z; As[kc + 3][r] = v.w;
        }
        *(float4*)&Bs[brow][bcol] = *(const float4*)(W + (size_t)(k0 + brow) * H + bn + bcol);
        __syncthreads();
        #pragma unroll
        for (int k = 0; k < 16; k++) {
            union { float f[8]; unsigned long long u[4]; } au;
            *(float4*)&au.f[0] = *(float4*)&As[k][ty * 8];
            *(float4*)&au.f[4] = *(float4*)&As[k][ty * 8 + 4];
            float4 b4 = *(float4*)&Bs[k][tx * 4];
            unsigned long long bb[4];
            bb[0] = bcast2(b4.x); bb[1] = bcast2(b4.y);
            bb[2] = bcast2(b4.z); bb[3] = bcast2(b4.w);
            #pragma unroll
            for (int p = 0; p < 4; p++) {
                #pragma unroll
                for (int j = 0; j < 4; j++)
                    ffma2(acc[p][j], au.u[p], bb[j]);
            }
        }
        __syncthreads();
    }
    float4 bv = *(const float4*)(bias + bn + tx * 4);
    #pragma unroll
    for (int p = 0; p < 4; p++) {
        float2 c0 = *(float2*)&acc[p][0];
        float2 c1 = *(float2*)&acc[p][1];
        float2 c2 = *(float2*)&acc[p][2];
        float2 c3 = *(float2*)&acc[p][3];
        int r0 = bm + ty * 8 + 2 * p;
        if (r0 < M) {
            float4 o;
            o.x = c0.x + bv.x; o.y = c1.x + bv.y;
            o.z = c2.x + bv.z; o.w = c3.x + bv.w;
            *(float4*)(C + (size_t)r0 * H + bn + tx * 4) = o;
        }
        if (r0 + 1 < M) {
            float4 o;
            o.x = c0.y + bv.x; o.y = c1.y + bv.y;
            o.z = c2.y + bv.z; o.w = c3.y + bv.w;
            *(float4*)(C + (size_t)(r0 + 1) * H + bn + tx * 4) = o;
        }
    }
}

// ---- gather/scatter GEMM for the labeled rows: C[rows[m]] = A[rows[m]]@W + b
__global__ __launch_bounds__(256) void k_gemm_idx(const float* __restrict__ A,
                                                  const float* __restrict__ W,
                                                  const float* __restrict__ bias,
                                                  float* __restrict__ C,
                                                  const int* __restrict__ rows, int M) {
    __shared__ float As[16][128];
    __shared__ float Bs[16][64];
    const int bm = blockIdx.x * 128;
    const int bn = blockIdx.y * 64;
    const int tid = threadIdx.x;
    const int tx = tid & 15;
    const int ty = tid >> 4;
    const int r   = tid >> 1;
    const int kcb = (tid & 1) * 8;
    const int brow = tid >> 4;
    const int bcol = (tid & 15) << 2;

    int arow = (bm + r < M) ? rows[bm + r] : 0;

    float acc[8][4];
    #pragma unroll
    for (int i = 0; i < 8; i++)
        #pragma unroll
        for (int j = 0; j < 4; j++) acc[i][j] = 0.f;

    for (int k0 = 0; k0 < H; k0 += 16) {
        #pragma unroll
        for (int u = 0; u < 2; u++) {
            int kc = kcb + u * 4;
            float4 v = make_float4(0.f, 0.f, 0.f, 0.f);
            if (bm + r < M) v = *(const float4*)(A + (size_t)arow * H + k0 + kc);
            As[kc + 0][r] = v.x; As[kc + 1][r] = v.y;
            As[kc + 2][r] = v.z; As[kc + 3][r] = v.w;
        }
        *(float4*)&Bs[brow][bcol] = *(const float4*)(W + (size_t)(k0 + brow) * H + bn + bcol);
        __syncthreads();
        #pragma unroll
        for (int k = 0; k < 16; k++) {
            float a[8], b[4];
            *(float4*)&a[0] = *(float4*)&As[k][ty * 8];
            *(float4*)&a[4] = *(float4*)&As[k][ty * 8 + 4];
            *(float4*)&b[0] = *(float4*)&Bs[k][tx * 4];
            #pragma unroll
            for (int i = 0; i < 8; i++)
                #pragma unroll
                for (int j = 0; j < 4; j++)
                    acc[i][j] += a[i] * b[j];
        }
        __syncthreads();
    }
    float4 bv = *(const float4*)(bias + bn + tx * 4);
    #pragma unroll
    for (int i = 0; i < 8; i++) {
        int m = bm + ty * 8 + i;
        if (m < M) {
            int crow = rows[m];
            float4 o;
            o.x = acc[i][0] + bv.x; o.y = acc[i][1] + bv.y;
            o.z = acc[i][2] + bv.z; o.w = acc[i][3] + bv.w;
            *(float4*)(C + (size_t)crow * H + bn + tx * 4) = o;
        }
    }
}

// ---------------- aggregation: x[v] = sum over in-edges of h[src] ------------
__global__ __launch_bounds__(256) void k_aggr() {
    int w = (blockIdx.x * blockDim.x + threadIdx.x) >> 5;
    int lane = threadIdx.x & 31;
    if (w >= NN) return;
    int s = g_start[w];
    int e = s + g_deg[w];
    const float4* __restrict__ h4 = (const float4*)g_h;
    float4 a0 = make_float4(0.f, 0.f, 0.f, 0.f);
    float4 a1 = make_float4(0.f, 0.f, 0.f, 0.f);
    #pragma unroll 4
    for (int i = s; i < e; i++) {
        int src = __ldg(&g_csr[i]);
        float4 v0 = h4[(size_t)src * 64 + lane];
        float4 v1 = h4[(size_t)src * 64 + 32 + lane];
        a0.x += v0.x; a0.y += v0.y; a0.z += v0.z; a0.w += v0.w;
        a1.x += v1.x; a1.y += v1.y; a1.z += v1.z; a1.w += v1.w;
    }
    float4* x4 = (float4*)g_x;
    x4[(size_t)w * 64 + lane] = a0;
    x4[(size_t)w * 64 + 32 + lane] = a1;
}

// ---------------- final gather: out[r] = x[pos[r]] ---------------------------
__global__ void k_out(const int* __restrict__ pos, float* __restrict__ out) {
    int rr = blockIdx.x;           // 0..8191
    int t = threadIdx.x;           // 0..63 float4 lanes
    int node = pos[rr];
    ((float4*)out)[(size_t)rr * 64 + t] = ((const float4*)g_x)[(size_t)node * 64 + t];
}

// ---------------- launch -----------------------------------------------------
extern "C" void kernel_launch(void* const* d_in, const int* in_sizes, int n_in,
                              void* d_out, int out_size) {
    const float* x     = (const float*)d_in[0];
    const float* f0w   = (const float*)d_in[1];
    const float* f0b   = (const float*)d_in[2];
    const float* f1w   = (const float*)d_in[3];
    const float* f1b   = (const float*)d_in[4];
    const float* convw = (const float*)d_in[5];
    const float* convb = (const float*)d_in[6];
    const int*   esrc  = (const int*)d_in[7];
    const int*   edst  = (const int*)d_in[8];
    const int*   pos   = (const int*)d_in[9];
    float* out = (float*)d_out;

    static float *hbuf = nullptr, *xbuf = nullptr, *W0, *W1, *B0, *B1;
    if (!hbuf) {
        cudaGetSymbolAddress((void**)&hbuf, g_h);
        cudaGetSymbolAddress((void**)&xbuf, g_x);
        cudaGetSymbolAddress((void**)&W0, g_W0);
        cudaGetSymbolAddress((void**)&W1, g_W1);
        cudaGetSymbolAddress((void**)&B0, g_B0);
        cudaGetSymbolAddress((void**)&B1, g_B1);
    }

    // CSR build
    k_zero<<<(NN + 255) / 256, 256>>>();
    k_hist<<<(NE + 255) / 256, 256>>>(edst);
    k_scan1<<<(NN + 1023) / 1024, 1024>>>();
    k_scan2<<<1, 64>>>();
    k_scan3<<<(NN + 1023) / 1024, 1024>>>();
    k_scatter<<<(NE + 255) / 256, 256>>>(esrc, edst);

    // fold (f0,f1) through conv
    k_fusew<<<dim3(H, NL, 2), H>>>(f0w, f1w, convw);
    k_fuseb<<<dim3(1, NL, 2), H>>>(f0b, f1b, convw, convb);

    const float* xin = x;
    for (int l = 0; l < NL; l++) {
        k_gemm<<<dim3((NN + 127) / 128, H / 64), 256>>>(
            xin, W0 + (size_t)l * H * H, B0 + l * H, hbuf, NN);
        k_gemm_idx<<<dim3(NIDX / 128, H / 64), 256>>>(
            xin, W1 + (size_t)l * H * H, B1 + l * H, hbuf, pos, NIDX);
        k_aggr<<<(NN * 32 + 255) / 256, 256>>>();
        xin = xbuf;
    }
    k_out<<<NIDX, 64>>>(pos, out);
}

// round 9
// speedup vs baseline: 1.5552x; 1.1220x over previous
#include <cuda_runtime.h>
#include <cuda_bf16.h>
#include <cstdint>

#define NN   50000
#define NE   800000
#define H    256
#define NL   3
#define NIDX 8192   // N_PAIRS * 2
#define NLW  ((NN + 31) / 32)
#define MAINBX 391  // ceil(NN/128); idx blocks follow

// ---------------- scratch (static device globals; no allocation) -------------
__device__ float g_h[(size_t)NN * H];     // 51.2 MB  (post-conv features)
__device__ float g_x[(size_t)NN * H];     // 51.2 MB  (aggregated features)
__device__ int   g_deg[NN];
__device__ int   g_fill[NN];
__device__ int   g_start[NN];             // exclusive CSR row start
__device__ int   g_blksum[64];            // per-block scan partials
__device__ int   g_csr[NE];               // src node per dst-sorted slot
__device__ unsigned g_lbl[NLW];           // bitmap: node in pos (labeled + needed)
__device__ float g_W0[NL * H * H];        // f0_w @ conv_w
__device__ float g_W1[NL * H * H];        // f1_w @ conv_w
__device__ float g_B0[NL * H];            // f0_b @ conv_w + conv_b
__device__ float g_B1[NL * H];            // f1_b @ conv_w + conv_b

// ---------------- packed fp32x2 helpers (Blackwell base ISA) -----------------
__device__ __forceinline__ void ffma2(unsigned long long& d, unsigned long long a,
                                      unsigned long long b) {
    asm("fma.rn.f32x2 %0, %1, %2, %3;" : "=l"(d) : "l"(a), "l"(b), "l"(d));
}
__device__ __forceinline__ unsigned long long bcast2(float x) {
    unsigned long long r;
    asm("mov.b64 %0, {%1, %1};" : "=l"(r) : "f"(x));
    return r;
}

// ---------------- CSR construction ------------------------------------------
__global__ void k_zero() {
    int i = blockIdx.x * blockDim.x + threadIdx.x;
    if (i < NN) { g_deg[i] = 0; g_fill[i] = 0; }
    if (i < NLW) g_lbl[i] = 0u;
}

__global__ void k_hist(const int* __restrict__ dst) {
    int e = blockIdx.x * blockDim.x + threadIdx.x;
    if (e < NE) atomicAdd(&g_deg[dst[e]], 1);
}

__global__ void k_mark(const int* __restrict__ pos) {
    int i = blockIdx.x * blockDim.x + threadIdx.x;
    if (i < NIDX) {
        int n = pos[i];
        atomicOr(&g_lbl[n >> 5], 1u << (n & 31));
    }
}

// phase 1: per-block (1024) inclusive scan -> local exclusive + block total
__global__ void k_scan1() {
    __shared__ int s1[1024];
    __shared__ int s2[1024];
    int t = threadIdx.x;
    int i = blockIdx.x * 1024 + t;
    int v = (i < NN) ? g_deg[i] : 0;
    s1[t] = v;
    __syncthreads();
    int* a = s1; int* b = s2;
    #pragma unroll
    for (int off = 1; off < 1024; off <<= 1) {
        int x = a[t];
        if (t >= off) x += a[t - off];
        b[t] = x;
        __syncthreads();
        int* tmp = a; a = b; b = tmp;
    }
    int incl = a[t];
    if (i < NN) g_start[i] = incl - v;           // block-local exclusive
    if (t == 1023) g_blksum[blockIdx.x] = incl;  // block total
}

// phase 2: exclusive scan of 49 block totals (single block)
__global__ void k_scan2() {
    __shared__ int s[64];
    int t = threadIdx.x;                 // 64 threads
    int v = (t < 49) ? g_blksum[t] : 0;
    s[t] = v;
    __syncthreads();
    #pragma unroll
    for (int off = 1; off < 64; off <<= 1) {
        int x = s[t];
        int y = (t >= off) ? s[t - off] : 0;
        __syncthreads();
        s[t] = x + y;
        __syncthreads();
    }
    if (t < 49) g_blksum[t] = s[t] - v;  // exclusive
}

// phase 3: add block offsets
__global__ void k_scan3() {
    int i = blockIdx.x * 1024 + threadIdx.x;
    if (i < NN) g_start[i] += g_blksum[blockIdx.x];
}

__global__ void k_scatter(const int* __restrict__ src, const int* __restrict__ dst) {
    int e = blockIdx.x * blockDim.x + threadIdx.x;
    if (e < NE) {
        int d = dst[e];
        int slot = g_start[d] + atomicAdd(&g_fill[d], 1);
        g_csr[slot] = src[e];
    }
}

// ---------------- weight folding (tiled): W = A @ conv_w ---------------------
// block handles 16 i-rows x all 256 j; grid (16, NL, 2)
__global__ void k_fusew(const float* __restrict__ f0w, const float* __restrict__ f1w,
                        const float* __restrict__ convw) {
    __shared__ float As[16][17];
    int l = blockIdx.y, which = blockIdx.z;
    const float* A = (which ? f1w : f0w) + (size_t)l * H * H;
    const float* B = convw + (size_t)l * H * H;
    float* C = (which ? g_W1 : g_W0) + (size_t)l * H * H;
    int i0 = blockIdx.x * 16;
    int j = threadIdx.x;
    float acc[16];
    #pragma unroll
    for (int i = 0; i < 16; i++) acc[i] = 0.f;
    for (int k0 = 0; k0 < H; k0 += 16) {
        {
            int ii = j >> 4, kk = j & 15;
            As[ii][kk] = A[(i0 + ii) * H + k0 + kk];
        }
        __syncthreads();
        #pragma unroll
        for (int kk = 0; kk < 16; kk++) {
            float b = B[(k0 + kk) * H + j];
            #pragma unroll
            for (int i = 0; i < 16; i++) acc[i] += As[i][kk] * b;
        }
        __syncthreads();
    }
    #pragma unroll
    for (int i = 0; i < 16; i++) C[(i0 + i) * H + j] = acc[i];
}

__global__ void k_fuseb(const float* __restrict__ f0b, const float* __restrict__ f1b,
                        const float* __restrict__ convw, const float* __restrict__ convb) {
    int l = blockIdx.y, which = blockIdx.z;
    const float* bb = (which ? f1b : f0b) + l * H;
    const float* B  = convw + (size_t)l * H * H;
    float* out = (which ? g_B1 : g_B0) + l * H;
    int j = threadIdx.x;
    float acc = convb[l * H + j];
    #pragma unroll 8
    for (int k = 0; k < H; k++) acc += bb[k] * B[k * H + j];
    out[j] = acc;
}

// ---------------- fused main+idx GEMM ----------------------------------------
// BM=128 BN=128 BK=16, 256 threads, 8x8 per thread (f32x2 packed along M).
// blocks x < MAINBX: C[row] = A[row]@W0+B0 for all rows with lbl-bit clear.
// blocks x >= MAINBX: C[pos[m]] = A[pos[m]]@W1+B1  (labeled rows, exclusive).
__global__ __launch_bounds__(256, 2) void k_gemm(
    const float* __restrict__ A,
    const float* __restrict__ W0l, const float* __restrict__ W1l,
    const float* __restrict__ B0l, const float* __restrict__ B1l,
    const int* __restrict__ pos, float* __restrict__ C, int M) {
    __shared__ float As[16][128];
    __shared__ float Bs[16][128];
    const bool idxmode = (blockIdx.x >= MAINBX);
    const int bm = idxmode ? (blockIdx.x - MAINBX) * 128 : blockIdx.x * 128;
    const int bn = blockIdx.y * 128;
    const float* W    = idxmode ? W1l : W0l;
    const float* bias = idxmode ? B1l : B0l;
    const int tid = threadIdx.x;
    const int tx = tid & 15;            // col group (8 cols)
    const int ty = tid >> 4;            // row group (8 rows)
    const int r   = tid >> 1;           // A-tile row this thread stages
    const int kcb = (tid & 1) * 8;      // A-tile k base

    // source row for staging
    int arow;
    bool rvalid;
    if (idxmode) { arow = __ldg(&pos[bm + r]); rvalid = true; }
    else         { arow = bm + r;              rvalid = (arow < M); }

    unsigned long long acc[4][8];
    #pragma unroll
    for (int p = 0; p < 4; p++)
        #pragma unroll
        for (int j = 0; j < 8; j++) acc[p][j] = 0ull;

    for (int k0 = 0; k0 < H; k0 += 16) {
        #pragma unroll
        for (int u = 0; u < 2; u++) {
            int kc = kcb + u * 4;
            float4 v = make_float4(0.f, 0.f, 0.f, 0.f);
            if (rvalid) v = *(const float4*)(A + (size_t)arow * H + k0 + kc);
            As[kc + 0][r] = v.x; As[kc + 1][r] = v.y;
            As[kc + 2][r] = v.z; As[kc + 3][r] = v.w;
        }
        #pragma unroll
        for (int u = 0; u < 2; u++) {
            int i = tid + u * 256;
            int brow = i >> 5, bcol = (i & 31) * 4;
            *(float4*)&Bs[brow][bcol] =
                *(const float4*)(W + (size_t)(k0 + brow) * H + bn + bcol);
        }
        __syncthreads();
        #pragma unroll
        for (int k = 0; k < 16; k++) {
            union { float f[8]; unsigned long long u[4]; } au;
            *(float4*)&au.f[0] = *(float4*)&As[k][ty * 8];
            *(float4*)&au.f[4] = *(float4*)&As[k][ty * 8 + 4];
            float4 b0 = *(float4*)&Bs[k][tx * 8];
            float4 b1 = *(float4*)&Bs[k][tx * 8 + 4];
            unsigned long long bb[8];
            bb[0] = bcast2(b0.x); bb[1] = bcast2(b0.y);
            bb[2] = bcast2(b0.z); bb[3] = bcast2(b0.w);
            bb[4] = bcast2(b1.x); bb[5] = bcast2(b1.y);
            bb[6] = bcast2(b1.z); bb[7] = bcast2(b1.w);
            #pragma unroll
            for (int p = 0; p < 4; p++) {
                #pragma unroll
                for (int j = 0; j < 8; j++)
                    ffma2(acc[p][j], au.u[p], bb[j]);
            }
        }
        __syncthreads();
    }

    float4 bv0 = *(const float4*)(bias + bn + tx * 8);
    float4 bv1 = *(const float4*)(bias + bn + tx * 8 + 4);
    #pragma unroll
    for (int p = 0; p < 4; p++) {
        float2 c[8];
        #pragma unroll
        for (int j = 0; j < 8; j++) c[j] = *(float2*)&acc[p][j];
        int m0 = bm + ty * 8 + 2 * p;
        #pragma unroll
        for (int half = 0; half < 2; half++) {
            int m = m0 + half;
            int crow;
            bool wr;
            if (idxmode) {
                crow = __ldg(&pos[m]);
                wr = true;
            } else {
                crow = m;
                wr = (m < M) && !((g_lbl[m >> 5] >> (m & 31)) & 1u);
            }
            if (wr) {
                float* cp = C + (size_t)crow * H + bn + tx * 8;
                float4 o;
                if (half == 0) {
                    o.x = c[0].x + bv0.x; o.y = c[1].x + bv0.y;
                    o.z = c[2].x + bv0.z; o.w = c[3].x + bv0.w;
                    *(float4*)cp = o;
                    o.x = c[4].x + bv1.x; o.y = c[5].x + bv1.y;
                    o.z = c[6].x + bv1.z; o.w = c[7].x + bv1.w;
                    *(float4*)(cp + 4) = o;
                } else {
                    o.x = c[0].y + bv0.x; o.y = c[1].y + bv0.y;
                    o.z = c[2].y + bv0.z; o.w = c[3].y + bv0.w;
                    *(float4*)cp = o;
                    o.x = c[4].y + bv1.x; o.y = c[5].y + bv1.y;
                    o.z = c[6].y + bv1.z; o.w = c[7].y + bv1.w;
                    *(float4*)(cp + 4) = o;
                }
            }
        }
    }
}

// ---------------- aggregation: x[v] = sum over in-edges of h[src] ------------
// filter!=0: only aggregate nodes whose lbl bit is set (final layer: out rows)
__global__ __launch_bounds__(256) void k_aggr(int filter) {
    int w = (blockIdx.x * blockDim.x + threadIdx.x) >> 5;
    int lane = threadIdx.x & 31;
    if (w >= NN) return;
    if (filter && !((g_lbl[w >> 5] >> (w & 31)) & 1u)) return;
    int s = g_start[w];
    int e = s + g_deg[w];
    const float4* __restrict__ h4 = (const float4*)g_h;
    float4 a0 = make_float4(0.f, 0.f, 0.f, 0.f);
    float4 a1 = make_float4(0.f, 0.f, 0.f, 0.f);
    #pragma unroll 4
    for (int i = s; i < e; i++) {
        int src = __ldg(&g_csr[i]);
        float4 v0 = h4[(size_t)src * 64 + lane];
        float4 v1 = h4[(size_t)src * 64 + 32 + lane];
        a0.x += v0.x; a0.y += v0.y; a0.z += v0.z; a0.w += v0.w;
        a1.x += v1.x; a1.y += v1.y; a1.z += v1.z; a1.w += v1.w;
    }
    float4* x4 = (float4*)g_x;
    x4[(size_t)w * 64 + lane] = a0;
    x4[(size_t)w * 64 + 32 + lane] = a1;
}

// ---------------- final gather: out[r] = x[pos[r]] ---------------------------
__global__ void k_out(const int* __restrict__ pos, float* __restrict__ out) {
    int rr = blockIdx.x;           // 0..8191
    int t = threadIdx.x;           // 0..63 float4 lanes
    int node = pos[rr];
    ((float4*)out)[(size_t)rr * 64 + t] = ((const float4*)g_x)[(size_t)node * 64 + t];
}

// ---------------- launch -----------------------------------------------------
extern "C" void kernel_launch(void* const* d_in, const int* in_sizes, int n_in,
                              void* d_out, int out_size) {
    const float* x     = (const float*)d_in[0];
    const float* f0w   = (const float*)d_in[1];
    const float* f0b   = (const float*)d_in[2];
    const float* f1w   = (const float*)d_in[3];
    const float* f1b   = (const float*)d_in[4];
    const float* convw = (const float*)d_in[5];
    const float* convb = (const float*)d_in[6];
    const int*   esrc  = (const int*)d_in[7];
    const int*   edst  = (const int*)d_in[8];
    const int*   pos   = (const int*)d_in[9];
    float* out = (float*)d_out;

    static float *hbuf = nullptr, *xbuf = nullptr, *W0, *W1, *B0, *B1;
    if (!hbuf) {
        cudaGetSymbolAddress((void**)&hbuf, g_h);
        cudaGetSymbolAddress((void**)&xbuf, g_x);
        cudaGetSymbolAddress((void**)&W0, g_W0);
        cudaGetSymbolAddress((void**)&W1, g_W1);
        cudaGetSymbolAddress((void**)&B0, g_B0);
        cudaGetSymbolAddress((void**)&B1, g_B1);
    }

    // CSR build + labeled bitmap
    k_zero<<<(NN + 255) / 256, 256>>>();
    k_hist<<<(NE + 255) / 256, 256>>>(edst);
    k_mark<<<(NIDX + 255) / 256, 256>>>(pos);
    k_scan1<<<(NN + 1023) / 1024, 1024>>>();
    k_scan2<<<1, 64>>>();
    k_scan3<<<(NN + 1023) / 1024, 1024>>>();
    k_scatter<<<(NE + 255) / 256, 256>>>(esrc, edst);

    // fold (f0,f1) through conv
    k_fusew<<<dim3(16, NL, 2), 256>>>(f0w, f1w, convw);
    k_fuseb<<<dim3(1, NL, 2), H>>>(f0b, f1b, convw, convb);

    const float* xin = x;
    for (int l = 0; l < NL; l++) {
        k_gemm<<<dim3(MAINBX + NIDX / 128, 2), 256>>>(
            xin, W0 + (size_t)l * H * H, W1 + (size_t)l * H * H,
            B0 + l * H, B1 + l * H, pos, hbuf, NN);
        k_aggr<<<(NN * 32 + 255) / 256, 256>>>(l == NL - 1 ? 1 : 0);
        xin = xbuf;
    }
    k_out<<<NIDX, 64>>>(pos, out);
}

// round 11
// speedup vs baseline: 1.6033x; 1.0309x over previous
#include <cuda_runtime.h>
#include <cuda_bf16.h>
#include <cstdint>

#define NN   50000
#define NE   800000
#define H    256
#define NL   3
#define NIDX 8192   // N_PAIRS * 2
#define NLW  ((NN + 31) / 32)
#define MAINBX 391          // ceil(NN/128)
#define TILE_X (MAINBX + NIDX / 128)   // 455 tiles per n-half
#define NT_TILES (TILE_X * 2)          // 910
#define GEMM_GRID 304

// ---------------- scratch (static device globals; no allocation) -------------
__device__ float g_h[(size_t)NN * H];
__device__ float g_x[(size_t)NN * H];
__device__ int   g_deg[NN];
__device__ int   g_fill[NN];
__device__ int   g_start[NN];
__device__ int   g_blksum[64];
__device__ int   g_csr[NE];
__device__ unsigned g_lbl[NLW];
__device__ int   g_tile[NL];           // persistent-GEMM work counters
__device__ float g_W0[NL * H * H];
__device__ float g_W1[NL * H * H];
__device__ float g_B0[NL * H];
__device__ float g_B1[NL * H];

// ---------------- packed fp32x2 helpers --------------------------------------
__device__ __forceinline__ void ffma2(unsigned long long& d, unsigned long long a,
                                      unsigned long long b) {
    asm("fma.rn.f32x2 %0, %1, %2, %3;" : "=l"(d) : "l"(a), "l"(b), "l"(d));
}
__device__ __forceinline__ unsigned long long bcast2(float x) {
    unsigned long long r;
    asm("mov.b64 %0, {%1, %1};" : "=l"(r) : "f"(x));
    return r;
}

// ---------------- CSR construction ------------------------------------------
__global__ void k_zero() {
    int i = blockIdx.x * blockDim.x + threadIdx.x;
    if (i < NN) { g_deg[i] = 0; g_fill[i] = 0; }
    if (i < NLW) g_lbl[i] = 0u;
    if (i < NL)  g_tile[i] = 0;
}

__global__ void k_hist(const int* __restrict__ dst) {
    int e = blockIdx.x * blockDim.x + threadIdx.x;
    if (e < NE) atomicAdd(&g_deg[dst[e]], 1);
}

__global__ void k_mark(const int* __restrict__ pos) {
    int i = blockIdx.x * blockDim.x + threadIdx.x;
    if (i < NIDX) {
        int n = pos[i];
        atomicOr(&g_lbl[n >> 5], 1u << (n & 31));
    }
}

__global__ void k_scan1() {
    __shared__ int s1[1024];
    __shared__ int s2[1024];
    int t = threadIdx.x;
    int i = blockIdx.x * 1024 + t;
    int v = (i < NN) ? g_deg[i] : 0;
    s1[t] = v;
    __syncthreads();
    int* a = s1; int* b = s2;
    #pragma unroll
    for (int off = 1; off < 1024; off <<= 1) {
        int x = a[t];
        if (t >= off) x += a[t - off];
        b[t] = x;
        __syncthreads();
        int* tmp = a; a = b; b = tmp;
    }
    int incl = a[t];
    if (i < NN) g_start[i] = incl - v;
    if (t == 1023) g_blksum[blockIdx.x] = incl;
}

__global__ void k_scan2() {
    __shared__ int s[64];
    int t = threadIdx.x;
    int v = (t < 49) ? g_blksum[t] : 0;
    s[t] = v;
    __syncthreads();
    #pragma unroll
    for (int off = 1; off < 64; off <<= 1) {
        int x = s[t];
        int y = (t >= off) ? s[t - off] : 0;
        __syncthreads();
        s[t] = x + y;
        __syncthreads();
    }
    if (t < 49) g_blksum[t] = s[t] - v;
}

__global__ void k_scan3() {
    int i = blockIdx.x * 1024 + threadIdx.x;
    if (i < NN) g_start[i] += g_blksum[blockIdx.x];
}

__global__ void k_scatter(const int* __restrict__ src, const int* __restrict__ dst) {
    int e = blockIdx.x * blockDim.x + threadIdx.x;
    if (e < NE) {
        int d = dst[e];
        int slot = g_start[d] + atomicAdd(&g_fill[d], 1);
        g_csr[slot] = src[e];
    }
}

// ---------------- weight folding (tiled) -------------------------------------
__global__ void k_fusew(const float* __restrict__ f0w, const float* __restrict__ f1w,
                        const float* __restrict__ convw) {
    __shared__ float As[16][17];
    int l = blockIdx.y, which = blockIdx.z;
    const float* A = (which ? f1w : f0w) + (size_t)l * H * H;
    const float* B = convw + (size_t)l * H * H;
    float* C = (which ? g_W1 : g_W0) + (size_t)l * H * H;
    int i0 = blockIdx.x * 16;
    int j = threadIdx.x;
    float acc[16];
    #pragma unroll
    for (int i = 0; i < 16; i++) acc[i] = 0.f;
    for (int k0 = 0; k0 < H; k0 += 16) {
        {
            int ii = j >> 4, kk = j & 15;
            As[ii][kk] = A[(i0 + ii) * H + k0 + kk];
        }
        __syncthreads();
        #pragma unroll
        for (int kk = 0; kk < 16; kk++) {
            float b = B[(k0 + kk) * H + j];
            #pragma unroll
            for (int i = 0; i < 16; i++) acc[i] += As[i][kk] * b;
        }
        __syncthreads();
    }
    #pragma unroll
    for (int i = 0; i < 16; i++) C[(i0 + i) * H + j] = acc[i];
}

__global__ void k_fuseb(const float* __restrict__ f0b, const float* __restrict__ f1b,
                        const float* __restrict__ convw, const float* __restrict__ convb) {
    int l = blockIdx.y, which = blockIdx.z;
    const float* bb = (which ? f1b : f0b) + l * H;
    const float* B  = convw + (size_t)l * H * H;
    float* out = (which ? g_B1 : g_B0) + l * H;
    int j = threadIdx.x;
    float acc = convb[l * H + j];
    #pragma unroll 8
    for (int k = 0; k < H; k++) acc += bb[k] * B[k * H + j];
    out[j] = acc;
}

// ---------------- persistent fused main+idx GEMM -----------------------------
// BM=128 BN=128 BK=32, 256 threads, 8x8 per thread (f32x2 packed along M).
// Double-buffered SMEM; A via register prefetch, B via cp.async.
// SMEM floats: As[2][32][128] @0, Bs[2][32][128] @8192, tile slot @16384.
#define SMEM_FLOATS (16384 + 4)
#define SMEM_BYTES  (SMEM_FLOATS * 4)

__global__ __launch_bounds__(256, 2) void k_gemm(
    const float* __restrict__ A,
    const float* __restrict__ W0l, const float* __restrict__ W1l,
    const float* __restrict__ B0l, const float* __restrict__ B1l,
    const int* __restrict__ pos, float* __restrict__ C, int layer) {
    extern __shared__ float sm[];
    float* Asm = sm;
    float* Bsm = sm + 8192;
    int* tslot = (int*)(sm + 16384);

    const int tid = threadIdx.x;
    const int tx = tid & 15;
    const int ty = tid >> 4;
    const int r   = tid >> 1;
    const int kcb = (tid & 1) * 16;

    for (;;) {
        if (tid == 0) *tslot = atomicAdd(&g_tile[layer], 1);
        __syncthreads();
        const int t = *tslot;
        __syncthreads();
        if (t >= NT_TILES) return;

        const int by = t / TILE_X;
        const int bx = t - by * TILE_X;
        const bool idxmode = (bx >= MAINBX);
        const int bm = (idxmode ? bx - MAINBX : bx) * 128;
        const int bn = by * 128;
        const float* W    = idxmode ? W1l : W0l;
        const float* bias = idxmode ? B1l : B0l;

        int arow;
        bool rvalid;
        if (idxmode) { arow = __ldg(&pos[bm + r]); rvalid = true; }
        else         { arow = bm + r;              rvalid = (arow < NN); }
        const float* aptr = A + (size_t)arow * H + kcb;

        float4 pf[4];
        auto loadA = [&](int c) {
            #pragma unroll
            for (int i = 0; i < 4; i++)
                pf[i] = rvalid ? *(const float4*)(aptr + c * 32 + 4 * i)
                               : make_float4(0.f, 0.f, 0.f, 0.f);
        };
        auto stsA = [&](int b) {
            float* dst = Asm + b * 4096;
            #pragma unroll
            for (int i = 0; i < 4; i++) {
                int kc = kcb + 4 * i;
                dst[(kc + 0) * 128 + r] = pf[i].x;
                dst[(kc + 1) * 128 + r] = pf[i].y;
                dst[(kc + 2) * 128 + r] = pf[i].z;
                dst[(kc + 3) * 128 + r] = pf[i].w;
            }
        };
        auto cpB = [&](int c, int b) {
            float* dstb = Bsm + b * 4096;
            #pragma unroll
            for (int u = 0; u < 4; u++) {
                int i = tid + u * 256;
                int br = i >> 5, bc = (i & 31) * 4;
                const float* src = W + (size_t)(c * 32 + br) * H + bn + bc;
                unsigned daddr = (unsigned)__cvta_generic_to_shared(dstb + br * 128 + bc);
                asm volatile("cp.async.ca.shared.global [%0], [%1], 16;"
                             :: "r"(daddr), "l"(src));
            }
            asm volatile("cp.async.commit_group;");
        };

        unsigned long long acc[4][8];
        #pragma unroll
        for (int p = 0; p < 4; p++)
            #pragma unroll
            for (int j = 0; j < 8; j++) acc[p][j] = 0ull;

        auto compute = [&](int cur) {
            const float* Ab = Asm + cur * 4096;
            const float* Bb = Bsm + cur * 4096;
            #pragma unroll 8
            for (int k = 0; k < 32; k++) {
                union { float f[8]; unsigned long long u[4]; } au;
                *(float4*)&au.f[0] = *(const float4*)(Ab + k * 128 + ty * 8);
                *(float4*)&au.f[4] = *(const float4*)(Ab + k * 128 + ty * 8 + 4);
                float4 b0 = *(const float4*)(Bb + k * 128 + tx * 8);
                float4 b1 = *(const float4*)(Bb + k * 128 + tx * 8 + 4);
                unsigned long long bb[8];
                bb[0] = bcast2(b0.x); bb[1] = bcast2(b0.y);
                bb[2] = bcast2(b0.z); bb[3] = bcast2(b0.w);
                bb[4] = bcast2(b1.x); bb[5] = bcast2(b1.y);
                bb[6] = bcast2(b1.z); bb[7] = bcast2(b1.w);
                #pragma unroll
                for (int p = 0; p < 4; p++)
                    #pragma unroll
                    for (int j = 0; j < 8; j++)
                        ffma2(acc[p][j], au.u[p], bb[j]);
            }
        };

        // prologue
        loadA(0);
        cpB(0, 0);
        stsA(0);
        loadA(1);
        cpB(1, 1);
        asm volatile("cp.async.wait_group 1;" ::: "memory");
        __syncthreads();

        for (int c = 0; c < 8; c++) {
            if (c < 7) stsA((c + 1) & 1);     // A(c+1) regs -> other buffer
            compute(c & 1);
            if (c < 7) asm volatile("cp.async.wait_group 0;" ::: "memory");
            __syncthreads();
            if (c < 6) { loadA(c + 2); cpB(c + 2, c & 1); }
        }

        // epilogue
        float4 bv0 = *(const float4*)(bias + bn + tx * 8);
        float4 bv1 = *(const float4*)(bias + bn + tx * 8 + 4);
        #pragma unroll
        for (int p = 0; p < 4; p++) {
            float2 cfr[8];
            #pragma unroll
            for (int j = 0; j < 8; j++) cfr[j] = *(float2*)&acc[p][j];
            int m0 = bm + ty * 8 + 2 * p;
            #pragma unroll
            for (int half = 0; half < 2; half++) {
                int m = m0 + half;
                int crow;
                bool wr;
                if (idxmode) {
                    crow = __ldg(&pos[m]);
                    wr = true;
                } else {
                    crow = m;
                    wr = (m < NN) && !((g_lbl[m >> 5] >> (m & 31)) & 1u);
                }
                if (wr) {
                    float* cp = C + (size_t)crow * H + bn + tx * 8;
                    float4 o;
                    if (half == 0) {
                        o.x = cfr[0].x + bv0.x; o.y = cfr[1].x + bv0.y;
                        o.z = cfr[2].x + bv0.z; o.w = cfr[3].x + bv0.w;
                        *(float4*)cp = o;
                        o.x = cfr[4].x + bv1.x; o.y = cfr[5].x + bv1.y;
                        o.z = cfr[6].x + bv1.z; o.w = cfr[7].x + bv1.w;
                        *(float4*)(cp + 4) = o;
                    } else {
                        o.x = cfr[0].y + bv0.x; o.y = cfr[1].y + bv0.y;
                        o.z = cfr[2].y + bv0.z; o.w = cfr[3].y + bv0.w;
                        *(float4*)cp = o;
                        o.x = cfr[4].y + bv1.x; o.y = cfr[5].y + bv1.y;
                        o.z = cfr[6].y + bv1.z; o.w = cfr[7].y + bv1.w;
                        *(float4*)(cp + 4) = o;
                    }
                }
            }
        }
    }
}

// ---------------- aggregation ------------------------------------------------
__global__ __launch_bounds__(256) void k_aggr(int filter) {
    int w = (blockIdx.x * blockDim.x + threadIdx.x) >> 5;
    int lane = threadIdx.x & 31;
    if (w >= NN) return;
    if (filter && !((g_lbl[w >> 5] >> (w & 31)) & 1u)) return;
    int s = g_start[w];
    int e = s + g_deg[w];
    const float4* __restrict__ h4 = (const float4*)g_h;
    float4 a0 = make_float4(0.f, 0.f, 0.f, 0.f);
    float4 a1 = make_float4(0.f, 0.f, 0.f, 0.f);
    #pragma unroll 4
    for (int i = s; i < e; i++) {
        int src = __ldg(&g_csr[i]);
        float4 v0 = h4[(size_t)src * 64 + lane];
        float4 v1 = h4[(size_t)src * 64 + 32 + lane];
        a0.x += v0.x; a0.y += v0.y; a0.z += v0.z; a0.w += v0.w;
        a1.x += v1.x; a1.y += v1.y; a1.z += v1.z; a1.w += v1.w;
    }
    float4* x4 = (float4*)g_x;
    x4[(size_t)w * 64 + lane] = a0;
    x4[(size_t)w * 64 + 32 + lane] = a1;
}

// ---------------- final gather ----------------------------------------------
__global__ void k_out(const int* __restrict__ pos, float* __restrict__ out) {
    int rr = blockIdx.x;
    int t = threadIdx.x;
    int node = pos[rr];
    ((float4*)out)[(size_t)rr * 64 + t] = ((const float4*)g_x)[(size_t)node * 64 + t];
}

// ---------------- launch -----------------------------------------------------
extern "C" void kernel_launch(void* const* d_in, const int* in_sizes, int n_in,
                              void* d_out, int out_size) {
    const float* x     = (const float*)d_in[0];
    const float* f0w   = (const float*)d_in[1];
    const float* f0b   = (const float*)d_in[2];
    const float* f1w   = (const float*)d_in[3];
    const float* f1b   = (const float*)d_in[4];
    const float* convw = (const float*)d_in[5];
    const float* convb = (const float*)d_in[6];
    const int*   esrc  = (const int*)d_in[7];
    const int*   edst  = (const int*)d_in[8];
    const int*   pos   = (const int*)d_in[9];
    float* out = (float*)d_out;

    static float *hbuf = nullptr, *xbuf = nullptr, *W0, *W1, *B0, *B1;
    if (!hbuf) {
        cudaGetSymbolAddress((void**)&hbuf, g_h);
        cudaGetSymbolAddress((void**)&xbuf, g_x);
        cudaGetSymbolAddress((void**)&W0, g_W0);
        cudaGetSymbolAddress((void**)&W1, g_W1);
        cudaGetSymbolAddress((void**)&B0, g_B0);
        cudaGetSymbolAddress((void**)&B1, g_B1);
        cudaFuncSetAttribute(k_gemm, cudaFuncAttributeMaxDynamicSharedMemorySize,
                             SMEM_BYTES);
    }

    // CSR build + labeled bitmap (+ tile counters reset)
    k_zero<<<(NN + 255) / 256, 256>>>();
    k_hist<<<(NE + 255) / 256, 256>>>(edst);
    k_mark<<<(NIDX + 255) / 256, 256>>>(pos);
    k_scan1<<<(NN + 1023) / 1024, 1024>>>();
    k_scan2<<<1, 64>>>();
    k_scan3<<<(NN + 1023) / 1024, 1024>>>();
    k_scatter<<<(NE + 255) / 256, 256>>>(esrc, edst);

    // fold (f0,f1) through conv
    k_fusew<<<dim3(16, NL, 2), 256>>>(f0w, f1w, convw);
    k_fuseb<<<dim3(1, NL, 2), H>>>(f0b, f1b, convw, convb);

    const float* xin = x;
    for (int l = 0; l < NL; l++) {
        k_gemm<<<GEMM_GRID, 256, SMEM_BYTES>>>(
            xin, W0 + (size_t)l * H * H, W1 + (size_t)l * H * H,
            B0 + l * H, B1 + l * H, pos, hbuf, l);
        k_aggr<<<(NN * 32 + 255) / 256, 256>>>(l == NL - 1 ? 1 : 0);
        xin = xbuf;
    }
    k_out<<<NIDX, 64>>>(pos, out);
}